// round 10
// baseline (speedup 1.0000x reference)
#include <cuda_runtime.h>
#include <math_constants.h>
#include <cstdint>

// 5x5 per-channel max (cv2.dilate), SAME padding, (64,384,384,3) fp32.
// Fused dim L = W*C = 1152 floats = 288 float4; 144 blocks of 8 words.
// R6 compute core: thread owns 8 fused words (2 float4); vertical 5-max via
// 5-deep register ring over a pure LDG stream (y-border clamp == -inf pad);
// horizontal 5-max (taps +-3,+-6) via 12 shuffles / 8 outputs (stride-3).
// NEW: exact-single-wave persistent warp mapping. Grid = 592 = 4*148 blocks,
// 5 warps each = 2960 slots; warp W < 2880 handles (xpos 0..4, b 0..63,
// seg 0..8) with 43-row strips (last 40) -> halo factor 1.093, no wave tail.

#define B_    64
#define H_    384
#define L_    1152
#define L4_   288
#define NB8   144
#define NW    5
#define NT    (NW * 32)        // 160
#define NBLK  592              // 4 * 148 SMs
#define NSEG  9
#define SEGR  43               // rows per seg (last seg: 384 - 8*43 = 40)
#define FULL  0xffffffffu

__device__ __forceinline__ float4 f4max(float4 a, float4 b) {
    return make_float4(fmaxf(a.x, b.x), fmaxf(a.y, b.y),
                       fmaxf(a.z, b.z), fmaxf(a.w, b.w));
}

__global__ __launch_bounds__(NT, 4)
void dilate5_kernel(const float* __restrict__ in,
                    const int* __restrict__ kptr,
                    float* __restrict__ out)
{
    const int k  = *kptr;
    const int t  = threadIdx.x;
    const int w  = t >> 5;
    const int l  = t & 31;

    const int W = blockIdx.x * NW + w;       // global warp id
    if (W >= 5 * B_ * NSEG) return;          // 2880 work units

    const int xpos = W % 5;
    const int rem  = W / 5;
    const int b    = rem % B_;
    const int seg  = rem / B_;               // 0..8

    const int y0  = seg * SEGR;
    const int TYv = (H_ - y0 < SEGR) ? (H_ - y0) : SEGR;   // 43 or 40
    const int TOT = TYv + 4;

    const int o  = 30 * xpos + l - 1;        // 8-word block index (-1 .. 150)
    const int c0 = 2 * o;
    const int c1 = 2 * o + 1;

    if (k == 5) {
        const bool ok0   = (o >= 0) && (c0 < L4_);
        const bool ok1   = (o >= 0) && (c1 < L4_);
        const bool st_ok = (l >= 1) && (l <= 30) && (o >= 0) && (o < NB8);

        const float4* inb  = (const float4*)in  + (size_t)b * H_ * L4_;
        float4*       outb = (float4*)      out + (size_t)b * H_ * L4_;
        const float   NI   = -CUDART_INF_F;
        const float4  NEG4 = make_float4(NI, NI, NI, NI);

        float4 ringA[5], ringB[5];

        // steady loop, unrolled by 5 so ring indices are static:
        // (base + i) % 5 == i  because base % 5 == 0
        for (int base = 0; base < 50; base += 5) {
            #pragma unroll
            for (int i = 0; i < 5; ++i) {
                const int s = base + i;
                if (s < TOT) {
                    int y = y0 - 2 + s;
                    y = (y < 0) ? 0 : ((y > H_ - 1) ? H_ - 1 : y);   // clamp pad

                    float4 vA = NEG4, vB = NEG4;
                    if (ok0) vA = __ldg(&inb[(size_t)y * L4_ + c0]);
                    if (ok1) vB = __ldg(&inb[(size_t)y * L4_ + c1]);
                    ringA[i] = vA;
                    ringB[i] = vB;

                    if (s >= 4) {
                        const float4 mA = f4max(f4max(f4max(ringA[0], ringA[1]),
                                                      f4max(ringA[2], ringA[3])),
                                                ringA[4]);
                        const float4 mB = f4max(f4max(f4max(ringB[0], ringB[1]),
                                                      f4max(ringB[2], ringB[3])),
                                                ringB[4]);
                        const float v0 = mA.x, v1 = mA.y, v2 = mA.z, v3 = mA.w;
                        const float v4 = mB.x, v5 = mB.y, v6 = mB.z, v7 = mB.w;

                        // left words -6..-1 (left lane's v2..v7)
                        const float l0 = __shfl_up_sync(FULL, v2, 1);
                        const float l1 = __shfl_up_sync(FULL, v3, 1);
                        const float l2 = __shfl_up_sync(FULL, v4, 1);
                        const float l3 = __shfl_up_sync(FULL, v5, 1);
                        const float l4 = __shfl_up_sync(FULL, v6, 1);
                        const float l5 = __shfl_up_sync(FULL, v7, 1);
                        // right words 8..13 (right lane's v0..v5)
                        const float r0 = __shfl_down_sync(FULL, v0, 1);
                        const float r1 = __shfl_down_sync(FULL, v1, 1);
                        const float r2 = __shfl_down_sync(FULL, v2, 1);
                        const float r3 = __shfl_down_sync(FULL, v3, 1);
                        const float r4 = __shfl_down_sync(FULL, v4, 1);
                        const float r5 = __shfl_down_sync(FULL, v5, 1);

                        // m3[j] = max(w[j], w[j+3])
                        const float m3_m6 = fmaxf(l0, l3);
                        const float m3_m5 = fmaxf(l1, l4);
                        const float m3_m4 = fmaxf(l2, l5);
                        const float m3_m3 = fmaxf(l3, v0);
                        const float m3_m2 = fmaxf(l4, v1);
                        const float m3_m1 = fmaxf(l5, v2);
                        const float m3_0  = fmaxf(v0, v3);
                        const float m3_1  = fmaxf(v1, v4);
                        const float m3_2  = fmaxf(v2, v5);
                        const float m3_3  = fmaxf(v3, v6);
                        const float m3_4  = fmaxf(v4, v7);
                        const float m3_5  = fmaxf(v5, r0);
                        const float m3_6  = fmaxf(v6, r1);
                        const float m3_7  = fmaxf(v7, r2);

                        // H[j] = max(m3[j-6], m3[j], w[j+6])
                        float4 oA, oB;
                        oA.x = fmaxf(m3_m6, fmaxf(m3_0, v6));
                        oA.y = fmaxf(m3_m5, fmaxf(m3_1, v7));
                        oA.z = fmaxf(m3_m4, fmaxf(m3_2, r0));
                        oA.w = fmaxf(m3_m3, fmaxf(m3_3, r1));
                        oB.x = fmaxf(m3_m2, fmaxf(m3_4, r2));
                        oB.y = fmaxf(m3_m1, fmaxf(m3_5, r3));
                        oB.z = fmaxf(m3_0,  fmaxf(m3_6, r4));
                        oB.w = fmaxf(m3_1,  fmaxf(m3_7, r5));

                        if (st_ok) {
                            const size_t rowo = (size_t)(y0 + s - 4) * L4_;
                            outb[rowo + c0] = oA;
                            outb[rowo + c1] = oB;
                        }
                    }
                }
            }
            if (base + 5 >= TOT) break;
        }
    } else {
        // ---------------- generic fallback (any k), SAME padding ----------------
        const int padL = (k - 1) / 2;
        const int C = 3, Wd = 384;
        if ((l >= 1) && (l <= 30) && o >= 0 && o < NB8) {
            for (int j = 0; j < 8; ++j) {
                const int x = 8 * o + j;
                const int ww = x / C;
                const int cc = x - ww * C;
                for (int ty = 0; ty < TYv; ++ty) {
                    const int oy = y0 + ty;
                    float m = -CUDART_INF_F;
                    for (int ky = 0; ky < k; ky++) {
                        const int gy = oy - padL + ky;
                        if (gy < 0 || gy >= H_) continue;
                        for (int kx = 0; kx < k; kx++) {
                            const int gw = ww - padL + kx;
                            if (gw < 0 || gw >= Wd) continue;
                            m = fmaxf(m, in[((size_t)b * H_ + gy) * L_ + gw * C + cc]);
                        }
                    }
                    out[((size_t)b * H_ + oy) * L_ + x] = m;
                }
            }
        }
    }
}

extern "C" void kernel_launch(void* const* d_in, const int* in_sizes, int n_in,
                              void* d_out, int out_size)
{
    const float* images = (const float*)d_in[0];
    const int*   kptr   = (const int*)d_in[1];
    float*       out    = (float*)d_out;

    dim3 grid(NBLK);           // 592 = 4 * 148 -> exactly one wave @ 4/SM
    dim3 block(NT);            // 160
    dilate5_kernel<<<grid, block>>>(images, kptr, out);
}

// round 11
// speedup vs baseline: 1.2235x; 1.2235x over previous
#include <cuda_runtime.h>
#include <math_constants.h>
#include <cstdint>

// 5x5 per-channel max (cv2.dilate), SAME padding, (64,384,384,3) fp32.
// Fused dim L = W*C = 1152 floats = 288 float4; 144 blocks of 8 words.
// R6 champion core: thread owns 8 fused words (2 float4); vertical 5-max via
// 5-deep register ring over a fully-unrolled LDG stream; horizontal 5-max
// (taps +-3,+-6) via 12 shuffles / 8 outputs (stride-3 trick).
// R11: interior/edge block specialization (interior path has affine y ->
// immediate-offset LDGs, no clamp ALU) + __stcs streaming stores.

#define B_    64
#define H_    384
#define L_    1152
#define L4_   288
#define NB8   144
#define TY    24
#define NW    5
#define NT    (NW * 32)        // 160
#define TOT   (TY + 4)         // 28
#define FULL  0xffffffffu

__device__ __forceinline__ float4 f4max(float4 a, float4 b) {
    return make_float4(fmaxf(a.x, b.x), fmaxf(a.y, b.y),
                       fmaxf(a.z, b.z), fmaxf(a.w, b.w));
}

// horizontal 5-max over 8 fused words using lane+-1 shuffles (stride-3 trick)
__device__ __forceinline__ void hmax8(const float4 mA, const float4 mB,
                                      float4& oA, float4& oB)
{
    const float v0 = mA.x, v1 = mA.y, v2 = mA.z, v3 = mA.w;
    const float v4 = mB.x, v5 = mB.y, v6 = mB.z, v7 = mB.w;

    // left neighbor words -6..-1 (left lane's v2..v7)
    const float l0 = __shfl_up_sync(FULL, v2, 1);
    const float l1 = __shfl_up_sync(FULL, v3, 1);
    const float l2 = __shfl_up_sync(FULL, v4, 1);
    const float l3 = __shfl_up_sync(FULL, v5, 1);
    const float l4 = __shfl_up_sync(FULL, v6, 1);
    const float l5 = __shfl_up_sync(FULL, v7, 1);
    // right neighbor words 8..13 (right lane's v0..v5)
    const float r0 = __shfl_down_sync(FULL, v0, 1);
    const float r1 = __shfl_down_sync(FULL, v1, 1);
    const float r2 = __shfl_down_sync(FULL, v2, 1);
    const float r3 = __shfl_down_sync(FULL, v3, 1);
    const float r4 = __shfl_down_sync(FULL, v4, 1);
    const float r5 = __shfl_down_sync(FULL, v5, 1);

    // m3[j] = max(w[j], w[j+3])
    const float m3_m6 = fmaxf(l0, l3);
    const float m3_m5 = fmaxf(l1, l4);
    const float m3_m4 = fmaxf(l2, l5);
    const float m3_m3 = fmaxf(l3, v0);
    const float m3_m2 = fmaxf(l4, v1);
    const float m3_m1 = fmaxf(l5, v2);
    const float m3_0  = fmaxf(v0, v3);
    const float m3_1  = fmaxf(v1, v4);
    const float m3_2  = fmaxf(v2, v5);
    const float m3_3  = fmaxf(v3, v6);
    const float m3_4  = fmaxf(v4, v7);
    const float m3_5  = fmaxf(v5, r0);
    const float m3_6  = fmaxf(v6, r1);
    const float m3_7  = fmaxf(v7, r2);

    // H[j] = max(m3[j-6], m3[j], w[j+6])
    oA.x = fmaxf(m3_m6, fmaxf(m3_0, v6));
    oA.y = fmaxf(m3_m5, fmaxf(m3_1, v7));
    oA.z = fmaxf(m3_m4, fmaxf(m3_2, r0));
    oA.w = fmaxf(m3_m3, fmaxf(m3_3, r1));
    oB.x = fmaxf(m3_m2, fmaxf(m3_4, r2));
    oB.y = fmaxf(m3_m1, fmaxf(m3_5, r3));
    oB.z = fmaxf(m3_0,  fmaxf(m3_6, r4));
    oB.w = fmaxf(m3_1,  fmaxf(m3_7, r5));
}

__global__ __launch_bounds__(NT, 4)
void dilate5_kernel(const float* __restrict__ in,
                    const int* __restrict__ kptr,
                    float* __restrict__ out)
{
    const int k  = *kptr;
    const int t  = threadIdx.x;
    const int w  = t >> 5;
    const int l  = t & 31;
    const int o  = 30 * w + l - 1;       // 8-word block index (-1 .. 150)
    const int c0 = 2 * o;
    const int c1 = 2 * o + 1;
    const int b  = blockIdx.y;
    const int y0 = blockIdx.x * TY;

    if (k == 5) {
        const bool ok0   = (o >= 0) && (c0 < L4_);
        const bool ok1   = (o >= 0) && (c1 < L4_);
        const bool st_ok = (l >= 1) && (l <= 30) && (o >= 0) && (o < NB8);

        const float4* inb  = (const float4*)in  + (size_t)b * H_ * L4_;
        float4*       outb = (float4*)      out + (size_t)b * H_ * L4_;
        const float   NI   = -CUDART_INF_F;
        const float4  NEG4 = make_float4(NI, NI, NI, NI);

        float4 ringA[5], ringB[5];

        if (y0 >= 2 && y0 + TY + 2 <= H_) {
            // -------- interior blocks (14 of 16): affine y, no clamp --------
            const float4* base = inb + (size_t)(y0 - 2) * L4_;
            #pragma unroll
            for (int s = 0; s < TOT; ++s) {
                const float4* row = base + (size_t)s * L4_;
                float4 vA = NEG4, vB = NEG4;
                if (ok0) vA = __ldg(row + c0);
                if (ok1) vB = __ldg(row + c1);
                ringA[s % 5] = vA;
                ringB[s % 5] = vB;

                if (s >= 4) {
                    const float4 mA = f4max(f4max(f4max(ringA[0], ringA[1]),
                                                  f4max(ringA[2], ringA[3])), ringA[4]);
                    const float4 mB = f4max(f4max(f4max(ringB[0], ringB[1]),
                                                  f4max(ringB[2], ringB[3])), ringB[4]);
                    float4 oA, oB;
                    hmax8(mA, mB, oA, oB);
                    if (st_ok) {
                        float4* po = outb + (size_t)(y0 + s - 4) * L4_;
                        __stcs(po + c0, oA);
                        __stcs(po + c1, oB);
                    }
                }
            }
        } else {
            // -------- edge blocks (gx = 0 or 15): clamped y --------
            #pragma unroll
            for (int s = 0; s < TOT; ++s) {
                int y = y0 - 2 + s;
                y = (y < 0) ? 0 : ((y > H_ - 1) ? H_ - 1 : y);   // clamp == -inf pad
                const float4* row = inb + (size_t)y * L4_;
                float4 vA = NEG4, vB = NEG4;
                if (ok0) vA = __ldg(row + c0);
                if (ok1) vB = __ldg(row + c1);
                ringA[s % 5] = vA;
                ringB[s % 5] = vB;

                if (s >= 4) {
                    const float4 mA = f4max(f4max(f4max(ringA[0], ringA[1]),
                                                  f4max(ringA[2], ringA[3])), ringA[4]);
                    const float4 mB = f4max(f4max(f4max(ringB[0], ringB[1]),
                                                  f4max(ringB[2], ringB[3])), ringB[4]);
                    float4 oA, oB;
                    hmax8(mA, mB, oA, oB);
                    if (st_ok) {
                        float4* po = outb + (size_t)(y0 + s - 4) * L4_;
                        __stcs(po + c0, oA);
                        __stcs(po + c1, oB);
                    }
                }
            }
        }
    } else {
        // ---------------- generic fallback (any k), SAME padding ----------------
        const int padL = (k - 1) / 2;
        const int C = 3, W = 384;
        if ((l >= 1) && (l <= 30) && o >= 0 && o < NB8) {
            for (int j = 0; j < 8; ++j) {
                const int x = 8 * o + j;
                const int ww = x / C;
                const int cc = x - ww * C;
                for (int ty = 0; ty < TY; ++ty) {
                    const int oy = y0 + ty;
                    float m = -CUDART_INF_F;
                    for (int ky = 0; ky < k; ky++) {
                        const int gy = oy - padL + ky;
                        if (gy < 0 || gy >= H_) continue;
                        for (int kx = 0; kx < k; kx++) {
                            const int gw = ww - padL + kx;
                            if (gw < 0 || gw >= W) continue;
                            m = fmaxf(m, in[((size_t)b * H_ + gy) * L_ + gw * C + cc]);
                        }
                    }
                    out[((size_t)b * H_ + oy) * L_ + x] = m;
                }
            }
        }
    }
}

extern "C" void kernel_launch(void* const* d_in, const int* in_sizes, int n_in,
                              void* d_out, int out_size)
{
    const float* images = (const float*)d_in[0];
    const int*   kptr   = (const int*)d_in[1];
    float*       out    = (float*)d_out;

    dim3 grid(H_ / TY, B_);    // 16 x 64 = 1024 blocks
    dim3 block(NT);            // 160
    dilate5_kernel<<<grid, block>>>(images, kptr, out);
}